// round 4
// baseline (speedup 1.0000x reference)
#include <cuda_runtime.h>
#include <cstdint>
#include <cstddef>

// KVCacheManager update_cache, token-gen path.
//   L=2, B=4, H=8, M=4096, D=128, fp32
//   out shape: (2[kv], L, B, H, M, D)
//   out[kv,l,b,h,m,d] = (m == pos[b] && pos[b] < seq_len) ? latest[l,b,h,d]
//                                                         : cache[l,b,h,m,d]
//
// R4 strategy: the op is a pure D2D copy of 2x128MiB plus a 64KB point
// scatter. Route the bulk through the copy engines (cudaMemcpyAsync D2D,
// explicitly allowed + graph-capturable), which historically beat the SM
// LDG/STG path on mixed read/write streams (~85-90% vs our measured ~80%).
// Then a tiny fixup kernel overwrites the 128 scattered rows.

static constexpr size_t L = 2, B = 4, H = 8, M = 4096, D = 128;
static constexpr size_t CACHE_ELEMS = L * B * H * M * D;       // 33,554,432 floats
static constexpr size_t CACHE_BYTES = CACHE_ELEMS * sizeof(float); // 128 MiB

// Fixup: 128 warps, one warp per (kv,l,b,h) row. Each lane writes one float4
// (D=128 floats = 32 float4). Runs after the bulk copies (same stream).
__global__ void __launch_bounds__(1024)
kv_fixup_kernel(const float4* __restrict__ latest_k,
                const float4* __restrict__ latest_v,
                const int*    __restrict__ pos,       // (B,1)
                const int*    __restrict__ seq_len_p, // scalar (may be null)
                float4*       __restrict__ out)
{
    unsigned t    = blockIdx.x * blockDim.x + threadIdx.x;
    unsigned w    = t >> 5;          // warp id 0..127
    unsigned lane = t & 31u;
    if (w >= 128) return;

    unsigned kv = (w >> 6) & 1u;
    unsigned l  = (w >> 5) & 1u;
    unsigned b  = (w >> 3) & 3u;
    unsigned h  =  w       & 7u;

    int p = __ldg(&pos[b]);
    int S = seq_len_p ? __ldg(seq_len_p) : (int)M;
    if (p < 0 || p >= S) return;     // scatter only within the live bucket

    // latest_{k,v}: (L,B,H,1,D) -> float4 index ((l*B+b)*H+h)*32 + lane
    unsigned li = ((((l << 2) + b) << 3) + h) * 32u + lane;
    float4 val = kv ? __ldg(&latest_v[li]) : __ldg(&latest_k[li]);

    // out: (2,L,B,H,M,D) -> float4 index ((((kv*L+l)*B+b)*H+h)*M + p)*32 + lane
    size_t row = ((((size_t)kv * L + l) * B + b) * H + h) * M + (size_t)p;
    out[row * 32u + lane] = val;
}

extern "C" void kernel_launch(void* const* d_in, const int* in_sizes, int n_in,
                              void* d_out, int out_size)
{
    // metadata order: k_caches, v_caches, latest_k, latest_v, position_ids, seq_len
    const void*   k_cache  = d_in[0];
    const void*   v_cache  = d_in[1];
    const float4* latest_k = (const float4*)d_in[2];
    const float4* latest_v = (const float4*)d_in[3];
    const int*    pos      = (const int*)d_in[4];
    const int*    seq_len  = (n_in >= 6) ? (const int*)d_in[5] : nullptr;

    char* out = (char*)d_out;

    // Bulk: copy-engine D2D streams (graph-capturable, same stream -> ordered).
    cudaMemcpyAsync(out,               k_cache, CACHE_BYTES,
                    cudaMemcpyDeviceToDevice, 0);
    cudaMemcpyAsync(out + CACHE_BYTES, v_cache, CACHE_BYTES,
                    cudaMemcpyDeviceToDevice, 0);

    // Point scatter: 128 warps = 4096 threads.
    kv_fixup_kernel<<<4, 1024>>>(latest_k, latest_v, pos, seq_len,
                                 (float4*)d_out);
    (void)in_sizes; (void)out_size;
}

// round 5
// speedup vs baseline: 1.0732x; 1.0732x over previous
#include <cuda_runtime.h>
#include <cstdint>

// KVCacheManager update_cache, token-gen path.
//   L=2, B=4, H=8, M=4096, D=128, fp32
//   out shape: (2[kv], L, B, H, M, D)
//   out[kv,l,b,h,m,d] = (m == pos[b] && pos[b] < seq_len) ? latest[l,b,h,d]
//                                                         : cache[l,b,h,m,d]
//
// HBM-bound streaming copy with fused point-scatter. float4-vectorized.
// Linear float4 index bit layout (24 bits = 16,777,216 float4s):
//   d4 : bits [0:5)   (32 float4 per D=128 row)
//   m  : bits [5:17)  (4096)
//   h  : bits [17:20) (8)
//   b  : bits [20:22) (4)
//   l  : bit  [22]    (2)
//   kv : bit  [23]    (2)
// Within a warp all lanes share m,b -> scatter branch is warp-uniform.
//
// History:
//   R2 (best): VPT=2 grid-span strided, default cached lds/sts -> 75.8us, DRAM 80.7%
//   R3: +__ldcs/__stcs + block-contiguous VPT=4 -> 76.7us (neutral/slightly worse)
//   R4: copy-engine route -> 88us (CE same BW, copies serialize). Reverted.
// R5: exact R2 structure, single isolated change: __stcs on stores only
//     (write-once lines evicted first; read stream keeps L2 sectors).

static constexpr unsigned TOTAL_VEC4 = 1u << 24;       // 16,777,216 float4s
static constexpr unsigned HALF_MASK  = (1u << 23) - 1; // index within one cache
static constexpr unsigned THREADS    = 256;
static constexpr unsigned VEC_PER_THREAD = 2;
static constexpr unsigned GRID = TOTAL_VEC4 / (THREADS * VEC_PER_THREAD); // 32768

__device__ __forceinline__ float4 load_elem(
    unsigned i,
    const float4* __restrict__ k_cache,
    const float4* __restrict__ v_cache,
    const float4* __restrict__ latest_k,
    const float4* __restrict__ latest_v,
    const int* __restrict__ pos, int S)
{
    unsigned d4 = i & 31u;
    unsigned m  = (i >> 5)  & 4095u;
    unsigned h  = (i >> 17) & 7u;
    unsigned b  = (i >> 20) & 3u;
    unsigned l  = (i >> 22) & 1u;
    unsigned kv = (i >> 23) & 1u;
    unsigned ci = i & HALF_MASK;

    int p = __ldg(&pos[b]);
    if ((int)m == p && p < S) {
        // latest_{k,v}: (L,B,H,1,D) -> float4 index ((l*B+b)*H+h)*32 + d4
        unsigned li = ((((l << 2) + b) << 3) + h) * 32u + d4;
        return kv ? __ldg(&latest_v[li]) : __ldg(&latest_k[li]);
    }
    return kv ? __ldg(&v_cache[ci]) : __ldg(&k_cache[ci]);
}

__global__ void __launch_bounds__(THREADS)
kv_update_kernel(const float4* __restrict__ k_cache,
                 const float4* __restrict__ v_cache,
                 const float4* __restrict__ latest_k,
                 const float4* __restrict__ latest_v,
                 const int*    __restrict__ pos,
                 const int*    __restrict__ seq_len_p,
                 float4*       __restrict__ out)
{
    const unsigned span = GRID * THREADS;   // 8,388,608
    unsigned i0 = blockIdx.x * THREADS + threadIdx.x;
    unsigned i1 = i0 + span;

    int S = seq_len_p ? __ldg(seq_len_p) : 4096;

    // Two independent load chains -> MLP=2 per thread, fully coalesced.
    float4 v0 = load_elem(i0, k_cache, v_cache, latest_k, latest_v, pos, S);
    float4 v1 = load_elem(i1, k_cache, v_cache, latest_k, latest_v, pos, S);

    // Stores: written once, never re-read -> evict-first.
    __stcs(&out[i0], v0);
    __stcs(&out[i1], v1);
}

extern "C" void kernel_launch(void* const* d_in, const int* in_sizes, int n_in,
                              void* d_out, int out_size)
{
    // metadata order: k_caches, v_caches, latest_k, latest_v, position_ids, seq_len
    const float4* k_cache  = (const float4*)d_in[0];
    const float4* v_cache  = (const float4*)d_in[1];
    const float4* latest_k = (const float4*)d_in[2];
    const float4* latest_v = (const float4*)d_in[3];
    const int*    pos      = (const int*)d_in[4];
    const int*    seq_len  = (n_in >= 6) ? (const int*)d_in[5] : nullptr;
    float4*       out      = (float4*)d_out;

    kv_update_kernel<<<GRID, THREADS>>>(k_cache, v_cache, latest_k, latest_v,
                                        pos, seq_len, out);
    (void)in_sizes; (void)out_size;
}